// round 6
// baseline (speedup 1.0000x reference)
#include <cuda_runtime.h>

// ---------------------------------------------------------------------------
// TopographLoss: B=1, C=2, D=64, H=112, W=112
// paired = bin_pred + 2*bin_gt in {0:TN, 1:FP, 2:FN, 3:TP}
// CCL: 6-conn for cat 0, 26-conn otherwise. Label = min voxel index of comp.
//
// CRITICAL-REGION TEST EMULATES THE REFERENCE AS EXECUTED (jax x64 DISABLED):
// edge keys L*N+nl wrap in int32; SENT canonicalizes to N*N mod 2^32 = 2^28
// (N = 49*2^14). Only wrapped keys in [0, 2^28) survive (negative src is
// dropped by segment_sum OOB-drop); src=k/N in [0,334], dst=k%N decodes to a
// garbage voxel for wrapped keys; category taken from paired[dst]. Components
// with label > 334 therefore see fg_cnt=bg_cnt=0 -> always critical.
// distinct-count==1 is tested via min==max (dedup-invariant).
// Loss = mean over critical components of mean_{voxels in comp}(p - g)^2.
// ---------------------------------------------------------------------------

#define DD 64
#define HH 112
#define WW 112
#define NN (DD * HH * WW)        // 802816 = 3136 * 256 exactly
#define IMAX 0x7fffffff
#define MAXIT 3
#define SENTW 268435456u         // (N*N) mod 2^32 = 2^28

// ---- device scratch (no allocations allowed) ----
__device__ int            g_parent[NN];   // per-voxel component label (min idx)
__device__ unsigned char  g_paired[NN];
__device__ float          g_prob[NN];
__device__ int            g_tpmin[NN];    // per-src wrapped-edge dst min/max
__device__ int            g_tpmax[NN];
__device__ int            g_tnmin[NN];
__device__ int            g_tnmax[NN];
__device__ float          g_lsum[NN];
__device__ int            g_ccnt[NN];
__device__ float          g_regsum;
__device__ int            g_nreg;
__device__ int            g_flag[MAXIT + 1];

// ---------------------------------------------------------------------------
// K1: binarize, softmax prob of channel 1, init all scratch
// ---------------------------------------------------------------------------
__global__ void k_init(const float* __restrict__ pred, const int* __restrict__ tgt) {
    int i = blockIdx.x * blockDim.x + threadIdx.x;
    if (i >= NN) return;
    float p0 = pred[i];
    float p1 = pred[NN + i];
    int bp = (p1 > p0) ? 1 : 0;              // argmax over C: tie -> channel 0
    int bg = (tgt[i] == 1) ? 1 : 0;
    g_paired[i] = (unsigned char)(bp + 2 * bg);
    float m  = fmaxf(p0, p1);
    float e0 = expf(p0 - m);
    float e1 = expf(p1 - m);
    g_prob[i] = e1 / (e0 + e1);
    g_parent[i] = i;
    g_tpmin[i] = IMAX;
    g_tnmin[i] = IMAX;
    g_tpmax[i] = -1;
    g_tnmax[i] = -1;
    g_lsum[i] = 0.0f;
    g_ccnt[i] = 0;
    if (i == 0) { g_regsum = 0.0f; g_nreg = 0; }
    if (i <= MAXIT) g_flag[i] = (i == 0) ? 1 : 0;
}

// ---------------------------------------------------------------------------
// Union-find (ECL-CC style). Coherent (volatile -> L2) reads during unions.
// Parent values strictly decrease; hooks via CAS only on roots (hook larger
// root under smaller), so the final root of each component is its min voxel
// index. All unite calls are on genuine adjacency edges -> no false merges.
// ---------------------------------------------------------------------------
__device__ __forceinline__ int find_root_v(int x) {
    volatile int* P = g_parent;
    while (true) {
        int p = P[x];
        if (p == x) return x;
        int gp = P[p];
        if (gp == p) return p;
        P[x] = gp;      // path halving (benign: ancestor, smaller, same comp)
        x = gp;
    }
}

__device__ __forceinline__ void unite(int a, int b) {
    int ra = find_root_v(a);
    int rb = find_root_v(b);
    while (ra != rb) {
        if (ra > rb) { int t = ra; ra = rb; rb = t; }
        int old = atomicCAS(&g_parent[rb], rb, ra);  // hook rb under smaller ra
        if (old == rb || old == ra) return;
        rb = find_root_v(old);
        ra = find_root_v(ra);
    }
}

// K2: hook pass over 13 half-offsets (symmetric closure covers all 26)
__global__ void k_union() {
    int i = blockIdx.x * blockDim.x + threadIdx.x;
    if (i >= NN) return;
    int x = i % WW;
    int t = i / WW;
    int y = t % HH;
    int z = t / HH;
    int ci = g_paired[i];

    const int off[13][3] = {
        {0,0,1},{0,1,-1},{0,1,0},{0,1,1},
        {1,-1,-1},{1,-1,0},{1,-1,1},
        {1,0,-1},{1,0,0},{1,0,1},
        {1,1,-1},{1,1,0},{1,1,1}};
    const bool axis[13] = {true,false,true,false,
                           false,false,false,
                           false,true,false,
                           false,false,false};
#pragma unroll
    for (int k = 0; k < 13; k++) {
        int zz = z + off[k][0];
        int yy = y + off[k][1];
        int xx = x + off[k][2];
        if ((unsigned)zz < DD && (unsigned)yy < HH && (unsigned)xx < WW) {
            int j = (zz * HH + yy) * WW + xx;
            int cj = g_paired[j];
            // category 0 (TN) connects only via face neighbors (6-conn)
            if (cj == ci && (ci != 0 || axis[k])) {
                // Safe skip: equal (possibly stale) parent values are genuine
                // past tree memberships -> same tree -> already connected.
                if (g_parent[i] != g_parent[j]) unite(i, j);
            }
        }
    }
}

// K3: flatten parent pointers to roots (forest is final after K2)
__global__ void k_flatten() {
    int i = blockIdx.x * blockDim.x + threadIdx.x;
    if (i >= NN) return;
    int x = i;
    int p = g_parent[x];
    while (p != x) { x = p; p = g_parent[x]; }
    g_parent[i] = x;
}

// ---------------------------------------------------------------------------
// K3b: min-propagation insurance. UF can only split (never over-merge), so
// a label-min stencil over the same graph repairs any lost union. If UF was
// exact (empirically it is), iteration 0 finds no changes and the rest skip.
// ---------------------------------------------------------------------------
__global__ void k_prop(int it) {
    if (g_flag[it] == 0) return;
    int i = blockIdx.x * blockDim.x + threadIdx.x;
    if (i >= NN) return;
    int x = i % WW;
    int t = i / WW;
    int y = t % HH;
    int z = t / HH;
    int ci = g_paired[i];
    int cur = g_parent[i];
    int best = cur;

    const int off[26][3] = {
        {-1,-1,-1},{-1,-1,0},{-1,-1,1},{-1,0,-1},{-1,0,0},{-1,0,1},
        {-1,1,-1},{-1,1,0},{-1,1,1},
        {0,-1,-1},{0,-1,0},{0,-1,1},{0,0,-1},{0,0,1},
        {0,1,-1},{0,1,0},{0,1,1},
        {1,-1,-1},{1,-1,0},{1,-1,1},{1,0,-1},{1,0,0},{1,0,1},
        {1,1,-1},{1,1,0},{1,1,1}};
    const bool axis[26] = {
        false,false,false,false,true,false,false,false,false,
        false,true,false,true,true,false,true,false,
        false,false,false,false,true,false,false,false,false};
#pragma unroll
    for (int k = 0; k < 26; k++) {
        int zz = z + off[k][0];
        int yy = y + off[k][1];
        int xx = x + off[k][2];
        if ((unsigned)zz < DD && (unsigned)yy < HH && (unsigned)xx < WW) {
            int j = (zz * HH + yy) * WW + xx;
            if (g_paired[j] == ci && (ci != 0 || axis[k])) {
                int lj = g_parent[j];
                if (lj < best) best = lj;
            }
        }
    }
    int jc = g_parent[cur];        // pointer jump (same-component index)
    if (jc < best) best = jc;
    if (best < cur) {
        atomicMin(&g_parent[i], best);
        g_flag[it + 1] = 1;
    }
}

// ---------------------------------------------------------------------------
// K4: EXACT emulation of the executed reference's wrapped-int32 edge pass.
// For EVERY ordered 26-adjacent pair (v,u) with labels L != nl:
//   kw = (uint32)(L*N + nl)  (int32 wraparound)
//   survive iff kw < 2^28 (= SENT mod 2^32; negatives -> OOB src -> dropped)
//   s = kw / N (in [0,334]), d = kw % N, category = paired[d]
//   accumulate per-(s,cat) distinct-d min/max (count==1 <=> min==max).
// Monotone read-guards before atomics: stale reads only cause redundant
// atomics, never wrong skips.
// ---------------------------------------------------------------------------
__global__ void k_edges_wrap() {
    int i = blockIdx.x * blockDim.x + threadIdx.x;   // exact grid: i < NN
    int x = i % WW;
    int t = i / WW;
    int y = t % HH;
    int z = t / HH;
    int L = g_parent[i];
    unsigned base = (unsigned)L * (unsigned)NN;

#pragma unroll
    for (int dz = -1; dz <= 1; dz++) {
#pragma unroll
        for (int dy = -1; dy <= 1; dy++) {
#pragma unroll
            for (int dx = -1; dx <= 1; dx++) {
                if (dz == 0 && dy == 0 && dx == 0) continue;
                int zz = z + dz, yy = y + dy, xx = x + dx;
                if ((unsigned)zz < DD && (unsigned)yy < HH && (unsigned)xx < WW) {
                    int j = (zz * HH + yy) * WW + xx;
                    int nl = g_parent[j];
                    if (nl != L) {
                        unsigned kw = base + (unsigned)nl;   // wraps mod 2^32
                        if (kw < SENTW) {
                            int s = (int)(kw / (unsigned)NN);
                            int d = (int)(kw % (unsigned)NN);
                            int cat = g_paired[d];
                            if (cat == 3) {
                                if (d < g_tpmin[s]) atomicMin(&g_tpmin[s], d);
                                if (d > g_tpmax[s]) atomicMax(&g_tpmax[s], d);
                            } else if (cat == 0) {
                                if (d < g_tnmin[s]) atomicMin(&g_tnmin[s], d);
                                if (d > g_tnmax[s]) atomicMax(&g_tnmax[s], d);
                            }
                        }
                    }
                }
            }
        }
    }
}

// ---------------------------------------------------------------------------
// K5: critical voxels -> per-label (sum of (p-g)^2, count), warp-aggregated.
// crit = wrong & ~((fg_cnt==1) & (bg_cnt==1)) with the wrapped-edge counts.
// Labels > 334 have untouched entries (min=IMAX != max=-1) -> critical.
// ---------------------------------------------------------------------------
__global__ void k_crit() {
    int i = blockIdx.x * blockDim.x + threadIdx.x;   // exact grid: i < NN
    int c = g_paired[i];
    bool crit = false;
    int li = -1;
    float v = 0.0f;
    if (c == 1 || c == 2) {
        li = g_parent[i];
        bool ok = (g_tpmin[li] == g_tpmax[li]) && (g_tnmin[li] == g_tnmax[li]);
        if (!ok) {
            float g = (c == 2) ? 1.0f : 0.0f;
            float d = g_prob[i] - g;
            v = d * d;
            crit = true;
        }
    }
    int key = crit ? li : -1;
    unsigned grp = __match_any_sync(0xffffffffu, key);
    int lane = threadIdx.x & 31;
    int leader = __ffs(grp) - 1;
    float sum = v;
    int cnt = crit ? 1 : 0;
#pragma unroll 1
    for (int l = 0; l < 32; l++) {
        int   okey = __shfl_sync(0xffffffffu, key, l);
        float ov   = __shfl_sync(0xffffffffu, v, l);
        if (crit && l != lane && okey == key) { sum += ov; cnt += 1; }
    }
    if (crit && lane == leader) {
        atomicAdd(&g_lsum[key], sum);
        atomicAdd(&g_ccnt[key], cnt);
    }
}

// ---------------------------------------------------------------------------
// K6: reg_sum = sum lsum/ccnt over critical labels; n_reg = #(ccnt>0)
// ---------------------------------------------------------------------------
__global__ void k_reduce() {
    __shared__ float ssum[256];
    __shared__ int   scnt[256];
    int i = blockIdx.x * blockDim.x + threadIdx.x;
    float rs = 0.0f;
    int nr = 0;
    if (i < NN) {
        int c = g_ccnt[i];
        if (c > 0) { rs = g_lsum[i] / (float)c; nr = 1; }
    }
    ssum[threadIdx.x] = rs;
    scnt[threadIdx.x] = nr;
    __syncthreads();
    for (int s = 128; s > 0; s >>= 1) {
        if (threadIdx.x < s) {
            ssum[threadIdx.x] += ssum[threadIdx.x + s];
            scnt[threadIdx.x] += scnt[threadIdx.x + s];
        }
        __syncthreads();
    }
    if (threadIdx.x == 0) {
        if (ssum[0] != 0.0f) atomicAdd(&g_regsum, ssum[0]);
        if (scnt[0] != 0)    atomicAdd(&g_nreg, scnt[0]);
    }
}

__global__ void k_final(float* out) {
    if (threadIdx.x == 0 && blockIdx.x == 0) {
        int n = g_nreg;
        out[0] = (n > 0) ? (g_regsum / (float)n) : 0.0f;
    }
}

// ---------------------------------------------------------------------------
extern "C" void kernel_launch(void* const* d_in, const int* in_sizes, int n_in,
                              void* d_out, int out_size) {
    const float* pred = (const float*)d_in[0];   // (1,2,64,112,112) float32
    const int*   tgt  = (const int*)d_in[1];     // (1,64,112,112) int32
    if (n_in >= 2 && in_sizes[0] == NN && in_sizes[1] == 2 * NN) {
        pred = (const float*)d_in[1];
        tgt  = (const int*)d_in[0];
    }
    float* out = (float*)d_out;

    const int T = 256;
    const int G = NN / T;   // 3136, exact

    k_init<<<G, T>>>(pred, tgt);
    k_union<<<G, T>>>();
    k_flatten<<<G, T>>>();
    for (int it = 0; it < MAXIT; it++) k_prop<<<G, T>>>(it);
    k_edges_wrap<<<G, T>>>();
    k_crit<<<G, T>>>();
    k_reduce<<<G, T>>>();
    k_final<<<1, 32>>>(out);
}